// round 15
// baseline (speedup 1.0000x reference)
#include <cuda_runtime.h>
#include <cuda_bf16.h>
#include <cuda_fp16.h>
#include <math.h>
#include <stdint.h>

// ---------------- problem constants ----------------
#define NB    4
#define LQ    5440
#define CCH   256
#define NH    8
#define NL    4
#define NP    4
#define DH    32
#define LEN_IN 5440
#define MROWS (NB * LQ)     // 21760
#define QPB   8             // queries per sample block
#define K3    (3 * CCH)     // 768 physical split storage [t0|t1|t2]
#define KLOG3 (3 * CCH)

// ---------------- scratch ----------------
__device__ __half g_valueh[(size_t)MROWS * CCH];   // projected value, fp16
__device__ float g_off  [(size_t)MROWS * CCH];
__device__ float g_attn [(size_t)MROWS * 128];

__device__ __nv_bfloat16 g_Ain[(size_t)MROWS * K3];   // split3(input_flatten)
__device__ __nv_bfloat16 g_Aq3[(size_t)MROWS * K3];   // split3(query)  (attn TC)
__device__ __nv_bfloat16 g_As [(size_t)MROWS * K3];   // split(sampled), t0|t1 used
__device__ __nv_bfloat16 g_Btv[(size_t)CCH * K3];
__device__ __nv_bfloat16 g_Bta[(size_t)128 * K3];     // split3-T(w_attn)
__device__ __nv_bfloat16 g_Btw[(size_t)CCH * K3];

// x3 product schedule: t0s0 + t0s1 + t1s0
__device__ __constant__ int c_amap[3] = {0, 0, 1};
__device__ __constant__ int c_bmap[3] = {0, 1, 0};

// ---------------- fp32 -> bf16 splits ----------------
__device__ __forceinline__ void bf16_split3(float x, __nv_bfloat16& t0,
                                            __nv_bfloat16& t1, __nv_bfloat16& t2)
{
    t0 = __float2bfloat16(x);
    const float r1 = x - __bfloat162float(t0);
    t1 = __float2bfloat16(r1);
    t2 = __float2bfloat16(r1 - __bfloat162float(t1));
}

// inputf -> g_Ain (blocks [0,MROWS)), query -> g_Aq3 (blocks [MROWS,2*MROWS))
__global__ __launch_bounds__(256)
void splitA_kernel(const float* __restrict__ Xin, const float* __restrict__ Xq)
{
    const int b = blockIdx.x;
    const float* X;
    __nv_bfloat16* A3;
    int bb;
    if (b < MROWS) { X = Xin; A3 = g_Ain; bb = b; }
    else           { X = Xq;  A3 = g_Aq3; bb = b - MROWS; }
    const int idx = bb * 256 + threadIdx.x;
    const int m = idx >> 8;
    const int k = idx & 255;
    __nv_bfloat16 t0, t1, t2;
    bf16_split3(X[idx], t0, t1, t2);
    __nv_bfloat16* row = A3 + (size_t)m * K3;
    row[k] = t0; row[CCH + k] = t1; row[2 * CCH + k] = t2;
}

__device__ __forceinline__ void splitB_body(const float* W, __nv_bfloat16* B3t,
                                            int Nn, int e)
{
    const int k = e / Nn;
    const int n = e - k * Nn;
    __nv_bfloat16 s0, s1, s2;
    bf16_split3(W[e], s0, s1, s2);
    __nv_bfloat16* row = B3t + (size_t)n * K3;
    row[k] = s0; row[CCH + k] = s1; row[2 * CCH + k] = s2;
}

// w_val, w_out, w_attn splits in one launch (off stays fp32 SIMT)
__global__ __launch_bounds__(256)
void split_weights(const float* __restrict__ wv, const float* __restrict__ ww,
                   const float* __restrict__ wa)
{
    const int b = blockIdx.x;
    const int t = threadIdx.x;
    if (b < 256)      splitB_body(wv, g_Btv, CCH, b * 256 + t);
    else if (b < 512) splitB_body(ww, g_Btw, CCH, (b - 256) * 256 + t);
    else              splitB_body(wa, g_Bta, 128, (b - 512) * 256 + t);
}

// ---------------- packed dual-fp32 FMA (FFMA2 via PTX) ------------------------
__device__ __forceinline__ void fma2(uint64_t& d, uint64_t a, uint64_t b)
{
    asm("fma.rn.f32x2 %0, %1, %2, %0;" : "+l"(d) : "l"(a), "l"(b));
}

// ---------------- device body: fp32 SIMT GEMM (off only) ---------------------
#define BM  128
#define BN  128
#define BK2 16
#define TM  8
#define TN  8
#define KQ  256

__device__ __forceinline__
void simt_off_body(char* smemRaw, int crow, int ccol,
                   const float* __restrict__ A,
                   const float* __restrict__ Boff,
                   const float* __restrict__ bias_off,
                   float* __restrict__ Coff)
{
    float (*As)[BK2 * BM] = reinterpret_cast<float (*)[BK2 * BM]>(smemRaw);
    float (*Bs)[BK2 * BN] = reinterpret_cast<float (*)[BK2 * BN]>(
        smemRaw + 2 * BK2 * BM * sizeof(float));

    const int colOff = ccol * BN;

    const int tid = threadIdx.x;
    const int threadRow = tid / (BN / TN);
    const int threadCol = tid % (BN / TN);

    const int rowA  = tid >> 2;
    const int colA4 = (tid & 3) * 4;
    const int rowB  = tid >> 5;
    const int colB4 = (tid & 31) * 4;

    const float* gA0 = A + (size_t)(crow * BM + rowA)      * KQ + colA4;
    const float* gA1 = A + (size_t)(crow * BM + rowA + 64) * KQ + colA4;
    const float* gB0 = Boff + (size_t)rowB       * 256 + colOff + colB4;
    const float* gB1 = Boff + (size_t)(rowB + 8) * 256 + colOff + colB4;

    uint64_t accp[TM * (TN / 2)];
    #pragma unroll
    for (int i = 0; i < TM * (TN / 2); i++) accp[i] = 0ull;

    float4 a0 = *reinterpret_cast<const float4*>(gA0);
    float4 a1 = *reinterpret_cast<const float4*>(gA1);
    float4 b0 = *reinterpret_cast<const float4*>(gB0);
    float4 b1 = *reinterpret_cast<const float4*>(gB1);
    {
        const float av0[4] = {a0.x, a0.y, a0.z, a0.w};
        const float av1[4] = {a1.x, a1.y, a1.z, a1.w};
        #pragma unroll
        for (int j = 0; j < 4; j++) {
            As[0][(colA4 + j) * BM + rowA]      = av0[j];
            As[0][(colA4 + j) * BM + rowA + 64] = av1[j];
        }
        *reinterpret_cast<float4*>(&Bs[0][rowB * BN + colB4])       = b0;
        *reinterpret_cast<float4*>(&Bs[0][(rowB + 8) * BN + colB4]) = b1;
    }
    __syncthreads();

    #pragma unroll
    for (int it = 0; it < KQ / BK2; it++) {
        const int buf = it & 1;
        const bool more = (it + 1) < (KQ / BK2);
        if (more) {
            const int k0 = (it + 1) * BK2;
            a0 = *reinterpret_cast<const float4*>(gA0 + k0);
            a1 = *reinterpret_cast<const float4*>(gA1 + k0);
            b0 = *reinterpret_cast<const float4*>(gB0 + (size_t)k0 * 256);
            b1 = *reinterpret_cast<const float4*>(gB1 + (size_t)k0 * 256);
        }

        #pragma unroll
        for (int k = 0; k < BK2; k++) {
            const float4 m0 = *reinterpret_cast<const float4*>(
                &As[buf][k * BM + threadRow * TM]);
            const float4 m1 = *reinterpret_cast<const float4*>(
                &As[buf][k * BM + threadRow * TM + 4]);
            const uint64_t* bp = reinterpret_cast<const uint64_t*>(
                &Bs[buf][k * BN + threadCol * TN]);
            uint64_t bn[4];
            bn[0] = bp[0]; bn[1] = bp[1]; bn[2] = bp[2]; bn[3] = bp[3];

            const float mv[8] = {m0.x, m0.y, m0.z, m0.w, m1.x, m1.y, m1.z, m1.w};
            #pragma unroll
            for (int i = 0; i < TM; i++) {
                const uint32_t mu = __float_as_uint(mv[i]);
                uint64_t mm;
                asm("mov.b64 %0, {%1, %1};" : "=l"(mm) : "r"(mu));
                #pragma unroll
                for (int j2 = 0; j2 < TN / 2; j2++)
                    fma2(accp[i * (TN / 2) + j2], mm, bn[j2]);
            }
        }

        if (more) {
            const float av0[4] = {a0.x, a0.y, a0.z, a0.w};
            const float av1[4] = {a1.x, a1.y, a1.z, a1.w};
            #pragma unroll
            for (int j = 0; j < 4; j++) {
                As[buf ^ 1][(colA4 + j) * BM + rowA]      = av0[j];
                As[buf ^ 1][(colA4 + j) * BM + rowA + 64] = av1[j];
            }
            *reinterpret_cast<float4*>(&Bs[buf ^ 1][rowB * BN + colB4])       = b0;
            *reinterpret_cast<float4*>(&Bs[buf ^ 1][(rowB + 8) * BN + colB4]) = b1;
        }
        __syncthreads();
    }

    float bj[TN];
    #pragma unroll
    for (int j = 0; j < TN; j++)
        bj[j] = bias_off[colOff + threadCol * TN + j];

    #pragma unroll
    for (int i = 0; i < TM; i++) {
        const int row = crow * BM + threadRow * TM + i;
        float o[TN];
        #pragma unroll
        for (int j2 = 0; j2 < TN / 2; j2++) {
            uint32_t lo, hi;
            asm("mov.b64 {%0, %1}, %2;" : "=r"(lo), "=r"(hi)
                : "l"(accp[i * (TN / 2) + j2]));
            o[2 * j2]     = __uint_as_float(lo) + bj[2 * j2];
            o[2 * j2 + 1] = __uint_as_float(hi) + bj[2 * j2 + 1];
        }
        #pragma unroll
        for (int j = 0; j < TN; j += 4) {
            const int col = colOff + threadCol * TN + j;
            *reinterpret_cast<float4*>(&Coff[(size_t)row * 256 + col]) =
                make_float4(o[j], o[j + 1], o[j + 2], o[j + 3]);
        }
    }
}

// ---------------- device body: bf16x3 TC GEMM, cp.async 4-stage ---------------
#define GBK    32
#define GP     40
#define STAGES 4
#define OPELTS (128 * GP)
#define KSTEPS (KLOG3 / GBK)               // 24
#define GSMEM  (STAGES * 2 * OPELTS * 2)   // 81920 bytes

#define CP16(sm_, gp_) asm volatile( \
    "cp.async.cg.shared.global [%0], [%1], 16;" :: "r"(sm_), "l"(gp_))
#define CP_COMMIT()  asm volatile("cp.async.commit_group;")
#define CP_WAIT2()   asm volatile("cp.async.wait_group 2;")

// If Chalf != nullptr, write fp16 output there; else write fp32 to C.
__device__ __forceinline__
void tc_gemm_body(char* smemRaw, int m0, int n0, int Nn,
                  const __nv_bfloat16* __restrict__ A,
                  const __nv_bfloat16* __restrict__ Bt,
                  const float* __restrict__ bias,
                  float* __restrict__ C,
                  __half* __restrict__ Chalf)
{
    __nv_bfloat16* As_ = reinterpret_cast<__nv_bfloat16*>(smemRaw);
    __nv_bfloat16* Bs_ = As_ + STAGES * OPELTS;

    const int tid  = threadIdx.x;
    const int wid  = tid >> 5;
    const int lane = tid & 31;
    const int wm = (wid >> 2) * 64;
    const int wn = (wid & 3) * 32;
    const int g8  = lane >> 2;
    const int tig = lane & 3;

    const int lrow = tid >> 2;
    const int lseg = tid & 3;
    const __nv_bfloat16* gA0 = A  + (size_t)(m0 + lrow)      * K3 + lseg * 8;
    const __nv_bfloat16* gA1 = A  + (size_t)(m0 + lrow + 64) * K3 + lseg * 8;
    const __nv_bfloat16* gB0 = Bt + (size_t)(n0 + lrow)      * K3 + lseg * 8;
    const __nv_bfloat16* gB1 = Bt + (size_t)(n0 + lrow + 64) * K3 + lseg * 8;
    const uint32_t sA0 = (uint32_t)__cvta_generic_to_shared(
        &As_[lrow * GP + lseg * 8]);
    const uint32_t sB0 = (uint32_t)__cvta_generic_to_shared(
        &Bs_[lrow * GP + lseg * 8]);

    float c[4][4][4];
    #pragma unroll
    for (int mi = 0; mi < 4; mi++)
        #pragma unroll
        for (int ni = 0; ni < 4; ni++)
            #pragma unroll
            for (int r = 0; r < 4; r++) c[mi][ni][r] = 0.0f;

    auto load_stage = [&](int st) {
        const int slot = st & (STAGES - 1);
        const int k0   = st * GBK;
        const int seg  = k0 >> 8;
        const int ka   = c_amap[seg] * CCH + (k0 & 255);
        const int kb   = c_bmap[seg] * CCH + (k0 & 255);
        const uint32_t so = slot * OPELTS * 2;
        CP16(sA0 + so,               gA0 + ka);
        CP16(sA0 + so + 64 * GP * 2, gA1 + ka);
        CP16(sB0 + so,               gB0 + kb);
        CP16(sB0 + so + 64 * GP * 2, gB1 + kb);
    };

    load_stage(0); CP_COMMIT();
    load_stage(1); CP_COMMIT();
    load_stage(2); CP_COMMIT();

    for (int kt = 0; kt < KSTEPS; kt++) {
        CP_WAIT2();
        __syncthreads();
        const __nv_bfloat16* Asl = As_ + (kt & (STAGES - 1)) * OPELTS;
        const __nv_bfloat16* Bsl = Bs_ + (kt & (STAGES - 1)) * OPELTS;

        #pragma unroll
        for (int h = 0; h < 2; h++) {
            uint32_t afr[4][4], bfr[4][2];
            #pragma unroll
            for (int mi = 0; mi < 4; mi++) {
                const int rb = (wm + mi * 16 + g8) * GP + h * 16 + tig * 2;
                afr[mi][0] = *reinterpret_cast<const uint32_t*>(&Asl[rb]);
                afr[mi][1] = *reinterpret_cast<const uint32_t*>(&Asl[rb + 8 * GP]);
                afr[mi][2] = *reinterpret_cast<const uint32_t*>(&Asl[rb + 8]);
                afr[mi][3] = *reinterpret_cast<const uint32_t*>(&Asl[rb + 8 * GP + 8]);
            }
            #pragma unroll
            for (int ni = 0; ni < 4; ni++) {
                const int rb = (wn + ni * 8 + g8) * GP + h * 16 + tig * 2;
                bfr[ni][0] = *reinterpret_cast<const uint32_t*>(&Bsl[rb]);
                bfr[ni][1] = *reinterpret_cast<const uint32_t*>(&Bsl[rb + 8]);
            }
            #pragma unroll
            for (int mi = 0; mi < 4; mi++)
                #pragma unroll
                for (int ni = 0; ni < 4; ni++) {
                    asm volatile(
                        "mma.sync.aligned.m16n8k16.row.col.f32.bf16.bf16.f32 "
                        "{%0,%1,%2,%3}, {%4,%5,%6,%7}, {%8,%9}, {%0,%1,%2,%3};"
                        : "+f"(c[mi][ni][0]), "+f"(c[mi][ni][1]),
                          "+f"(c[mi][ni][2]), "+f"(c[mi][ni][3])
                        : "r"(afr[mi][0]), "r"(afr[mi][1]),
                          "r"(afr[mi][2]), "r"(afr[mi][3]),
                          "r"(bfr[ni][0]), "r"(bfr[ni][1]));
                }
        }

        if (kt + STAGES - 1 < KSTEPS) load_stage(kt + STAGES - 1);
        CP_COMMIT();
    }

    #pragma unroll
    for (int mi = 0; mi < 4; mi++) {
        const int row = m0 + wm + mi * 16 + g8;
        #pragma unroll
        for (int ni = 0; ni < 4; ni++) {
            const int col = n0 + wn + ni * 8 + tig * 2;
            const float b0 = bias[col], b1 = bias[col + 1];
            const float v00 = c[mi][ni][0] + b0, v01 = c[mi][ni][1] + b1;
            const float v10 = c[mi][ni][2] + b0, v11 = c[mi][ni][3] + b1;
            if (Chalf) {
                *reinterpret_cast<__half2*>(&Chalf[(size_t)row * Nn + col]) =
                    __floats2half2_rn(v00, v01);
                *reinterpret_cast<__half2*>(&Chalf[(size_t)(row + 8) * Nn + col]) =
                    __floats2half2_rn(v10, v11);
            } else {
                *reinterpret_cast<float2*>(&C[(size_t)row * Nn + col]) =
                    make_float2(v00, v01);
                *reinterpret_cast<float2*>(&C[(size_t)(row + 8) * Nn + col]) =
                    make_float2(v10, v11);
            }
        }
    }
}

// ---------------- mega kernel: TC value + TC attn + SIMT off -----------------
// 850 blocks. role = bid % 5: 0,1 -> TC value (340); 2 -> TC attn (170);
// 3,4 -> SIMT off (340).
__global__ __launch_bounds__(256)
void mega_gemm(const __nv_bfloat16* __restrict__ Ain,
               const __nv_bfloat16* __restrict__ Btv,
               const float* __restrict__ b_val,
               const __nv_bfloat16* __restrict__ Aq3,
               const __nv_bfloat16* __restrict__ Bta,
               const float* __restrict__ b_attn,
               const float* __restrict__ query,
               const float* __restrict__ Boff,
               const float* __restrict__ bias_off,
               float* __restrict__ Coff,
               float* __restrict__ Cattn)
{
    extern __shared__ char smemRaw[];
    const int bid  = blockIdx.x;
    const int role = bid % 5;
    const int grp  = bid / 5;          // 0..169
    if (role < 2) {
        const int idx = grp * 2 + role;        // 0..339
        tc_gemm_body(smemRaw, (idx >> 1) * 128, (idx & 1) * 128, CCH,
                     Ain, Btv, b_val, nullptr, g_valueh);
    } else if (role == 2) {
        tc_gemm_body(smemRaw, grp * 128, 0, 128,
                     Aq3, Bta, b_attn, Cattn, nullptr);
    } else {
        const int idx = grp * 2 + (role - 3);  // 0..339
        simt_off_body(smemRaw, idx >> 1, idx & 1,
                      query, Boff, bias_off, Coff);
    }
}

// ---------------- standalone TC GEMM (out projection, fp32 out) --------------
__global__ __launch_bounds__(256)
void gemm_bf16x3(int Nn,
                 const __nv_bfloat16* __restrict__ A,
                 const __nv_bfloat16* __restrict__ Bt,
                 const float* __restrict__ bias,
                 float* __restrict__ C)
{
    extern __shared__ char smemRaw[];
    tc_gemm_body(smemRaw, blockIdx.y * 128, blockIdx.x * 128, Nn,
                 A, Bt, bias, C, nullptr);
}

// ---------------- sampling: fp16 gathers, 8 queries/block --------------------
__global__ __launch_bounds__(256)
void sample_kernel(const float* __restrict__ refp)
{
    const int nq0 = blockIdx.x * QPB;
    const int tid = threadIdx.x;

    __shared__ float4 s_w[QPB * 128];
    __shared__ int4   s_t[QPB * 128];

    // ---------- phase 1: per (q,h,point) weights + indices ----------
    #pragma unroll
    for (int rep = 0; rep < QPB * 128 / 256; rep++) {   // 4 reps
        const int task = tid + rep * 256;
        const int q    = task >> 7;
        const int rest = task & 127;
        const int l    = (rest & 15) >> 2;
        const int nq   = nq0 + q;

        float logit = g_attn[(size_t)nq * 128 + rest];
        float mx = logit;
        #pragma unroll
        for (int m = 8; m; m >>= 1)
            mx = fmaxf(mx, __shfl_xor_sync(0xffffffffu, mx, m, 16));
        float e = __expf(logit - mx);
        float ssum = e;
        #pragma unroll
        for (int m = 8; m; m >>= 1)
            ssum += __shfl_xor_sync(0xffffffffu, ssum, m, 16);
        const float aw = e * (1.0f / ssum);

        const int W  = 64 >> l;
        const int S0 = (16384 - (16384 >> (2 * l))) / 3;

        const float2 off = *reinterpret_cast<const float2*>(
            &g_off[(size_t)nq * CCH + rest * 2]);
        const float2 rp  = *reinterpret_cast<const float2*>(
            &refp[((size_t)nq * NL + l) * 2]);

        const float locx = fminf(fmaxf(rp.x + off.x, 0.0f), 1.0f);
        const float locy = fminf(fmaxf(rp.y + off.y, 0.0f), 1.0f);
        const float x = locx * (float)W - 0.5f;
        const float y = locy * (float)W - 0.5f;
        const int xf = (int)floorf(x);
        const int yf = (int)floorf(y);
        const int x0i = min(max(xf,     0), W - 1);
        const int x1i = min(max(xf + 1, 0), W - 1);
        const int y0i = min(max(yf,     0), W - 1);
        const int y1i = min(max(yf + 1, 0), W - 1);
        const float wx1 = (float)x1i - x;
        const float wx0 = x - (float)x0i;
        const float wy1 = (float)y1i - y;
        const float wy0 = y - (float)y0i;

        s_w[task] = make_float4(wx1 * wy1 * aw, wx1 * wy0 * aw,
                                wx0 * wy1 * aw, wx0 * wy0 * aw);
        s_t[task] = make_int4(S0 + y0i * W + x0i,
                              S0 + y1i * W + x0i,
                              S0 + y0i * W + x1i,
                              S0 + y1i * W + x1i);
    }
    __syncthreads();

    // ---------- phase 2: fp16 gathers, 4 threads per (q,h), 8 halves each ----
    const int q  = tid >> 5;        // 0..7
    const int r  = tid & 31;
    const int h  = r >> 2;          // 0..7
    const int d8 = r & 3;           // 0..3 (8-half group)
    const int nq = nq0 + q;
    const int n  = nq / LQ;

    const __half* vb = g_valueh + (size_t)n * LEN_IN * CCH + h * DH + d8 * 8;

    float acc[8];
    #pragma unroll
    for (int j = 0; j < 8; j++) acc[j] = 0.0f;
    const int tb0 = q * 128 + h * 16;

    #pragma unroll
    for (int i = 0; i < 16; i++) {
        const float4 w  = s_w[tb0 + i];
        const int4   tt = s_t[tb0 + i];
        const uint4 ua = *reinterpret_cast<const uint4*>(vb + (size_t)tt.x * CCH);
        const uint4 ub = *reinterpret_cast<const uint4*>(vb + (size_t)tt.y * CCH);
        const uint4 uc = *reinterpret_cast<const uint4*>(vb + (size_t)tt.z * CCH);
        const uint4 ud = *reinterpret_cast<const uint4*>(vb + (size_t)tt.w * CCH);
        const __half2* ha = reinterpret_cast<const __half2*>(&ua);
        const __half2* hb = reinterpret_cast<const __half2*>(&ub);
        const __half2* hc = reinterpret_cast<const __half2*>(&uc);
        const __half2* hd = reinterpret_cast<const __half2*>(&ud);
        #pragma unroll
        for (int p = 0; p < 4; p++) {
            const float2 fa = __half22float2(ha[p]);
            const float2 fb = __half22float2(hb[p]);
            const float2 fc = __half22float2(hc[p]);
            const float2 fd = __half22float2(hd[p]);
            acc[2*p]   += w.x * fa.x + w.y * fb.x + w.z * fc.x + w.w * fd.x;
            acc[2*p+1] += w.x * fa.y + w.y * fb.y + w.z * fc.y + w.w * fd.y;
        }
    }

    // fused split (t0,t1 only — x3 out-GEMM never reads the t2 segment)
    __align__(8) __nv_bfloat16 t0[8], t1[8];
    #pragma unroll
    for (int j = 0; j < 8; j++) {
        t0[j] = __float2bfloat16(acc[j]);
        t1[j] = __float2bfloat16(acc[j] - __bfloat162float(t0[j]));
    }

    __nv_bfloat16* row = g_As + (size_t)nq * K3 + h * DH + d8 * 8;
    *reinterpret_cast<ushort4*>(row)           = *reinterpret_cast<ushort4*>(t0);
    *reinterpret_cast<ushort4*>(row + 4)       = *reinterpret_cast<ushort4*>(t0 + 4);
    *reinterpret_cast<ushort4*>(row + CCH)     = *reinterpret_cast<ushort4*>(t1);
    *reinterpret_cast<ushort4*>(row + CCH + 4) = *reinterpret_cast<ushort4*>(t1 + 4);
}

// ---------------- launch ------------------------------------------------------
extern "C" void kernel_launch(void* const* d_in, const int* in_sizes, int n_in,
                              void* d_out, int out_size)
{
    const float* query  = (const float*)d_in[0];
    const float* refp   = (const float*)d_in[1];
    const float* inputf = (const float*)d_in[2];
    const float* w_off  = (const float*)d_in[5];
    const float* b_off  = (const float*)d_in[6];
    const float* w_attn = (const float*)d_in[7];
    const float* b_attn = (const float*)d_in[8];
    const float* w_val  = (const float*)d_in[9];
    const float* b_val  = (const float*)d_in[10];
    const float* w_out  = (const float*)d_in[11];
    const float* b_out  = (const float*)d_in[12];
    float* out = (float*)d_out;

    cudaFuncSetAttribute(gemm_bf16x3,
                         cudaFuncAttributeMaxDynamicSharedMemorySize, GSMEM);
    cudaFuncSetAttribute(mega_gemm,
                         cudaFuncAttributeMaxDynamicSharedMemorySize, GSMEM);

    float *go, *ga;
    cudaGetSymbolAddress((void**)&go, g_off);
    cudaGetSymbolAddress((void**)&ga, g_attn);
    __nv_bfloat16 *ain, *aq3, *as, *btv, *bta, *btw;
    cudaGetSymbolAddress((void**)&ain, g_Ain);
    cudaGetSymbolAddress((void**)&aq3, g_Aq3);
    cudaGetSymbolAddress((void**)&as,  g_As);
    cudaGetSymbolAddress((void**)&btv, g_Btv);
    cudaGetSymbolAddress((void**)&bta, g_Bta);
    cudaGetSymbolAddress((void**)&btw, g_Btw);

    const dim3 blk(256);
    const dim3 gGemm256(2, MROWS / 128);

    // splits: weights (val/out/attn) + activations (input_flatten, query)
    split_weights<<<640, blk>>>(w_val, w_out, w_attn);
    splitA_kernel<<<2 * MROWS, blk>>>(inputf, query);

    // value (TC->fp16) + attn (TC->fp32) + off (SIMT fp32 FFMA2) — pipe overlap
    mega_gemm<<<850, blk, GSMEM>>>(ain, btv, b_val,
                                   aq3, bta, b_attn,
                                   query, w_off, b_off, go, ga);

    // sampling (fp16 gathers) + fused split of sampled output
    sample_kernel<<<MROWS / QPB, blk>>>(refp);

    // out = samp @ w_out + b_out                  (TC bf16x3, fp32 out)
    gemm_bf16x3<<<gGemm256, blk, GSMEM>>>(CCH, as, btw, b_out, out);
}

// round 16
// speedup vs baseline: 1.0059x; 1.0059x over previous
#include <cuda_runtime.h>
#include <cuda_bf16.h>
#include <cuda_fp16.h>
#include <math.h>
#include <stdint.h>

// ---------------- problem constants ----------------
#define NB    4
#define LQ    5440
#define CCH   256
#define NH    8
#define NL    4
#define NP    4
#define DH    32
#define LEN_IN 5440
#define MROWS (NB * LQ)     // 21760
#define QPB   8             // queries per sample block
#define K3    (3 * CCH)     // 768 physical split storage [t0|t1|t2]
#define KLOG3 (3 * CCH)

// ---------------- scratch ----------------
__device__ __half g_valueh[(size_t)MROWS * CCH];   // projected value, fp16
__device__ float g_off  [(size_t)MROWS * CCH];
__device__ float g_attn [(size_t)MROWS * 128];

__device__ __nv_bfloat16 g_Ain[(size_t)MROWS * K3];   // split3(input_flatten)
__device__ __nv_bfloat16 g_As [(size_t)MROWS * K3];   // split(sampled), t0|t1 used
__device__ __nv_bfloat16 g_Btv[(size_t)CCH * K3];
__device__ __nv_bfloat16 g_Btw[(size_t)CCH * K3];

// x3 product schedule: t0s0 + t0s1 + t1s0
__device__ __constant__ int c_amap[3] = {0, 0, 1};
__device__ __constant__ int c_bmap[3] = {0, 1, 0};

// ---------------- fp32 -> bf16 splits ----------------
__device__ __forceinline__ void bf16_split3(float x, __nv_bfloat16& t0,
                                            __nv_bfloat16& t1, __nv_bfloat16& t2)
{
    t0 = __float2bfloat16(x);
    const float r1 = x - __bfloat162float(t0);
    t1 = __float2bfloat16(r1);
    t2 = __float2bfloat16(r1 - __bfloat162float(t1));
}

__device__ __forceinline__ void splitB_body(const float* W, __nv_bfloat16* B3t,
                                            int Nn, int e)
{
    const int k = e / Nn;
    const int n = e - k * Nn;
    __nv_bfloat16 s0, s1, s2;
    bf16_split3(W[e], s0, s1, s2);
    __nv_bfloat16* row = B3t + (size_t)n * K3;
    row[k] = s0; row[CCH + k] = s1; row[2 * CCH + k] = s2;
}

// one launch: w_val split, w_out split, split3(input_flatten)
__global__ __launch_bounds__(256)
void split_all(const float* __restrict__ wv, const float* __restrict__ ww,
               const float* __restrict__ Xin)
{
    const int b = blockIdx.x;
    const int t = threadIdx.x;
    if (b < 256)      { splitB_body(wv, g_Btv, CCH, b * 256 + t); return; }
    if (b < 512)      { splitB_body(ww, g_Btw, CCH, (b - 256) * 256 + t); return; }
    const int idx = (b - 512) * 256 + t;
    const int m = idx >> 8;
    const int k = idx & 255;
    __nv_bfloat16 t0, t1, t2;
    bf16_split3(Xin[idx], t0, t1, t2);
    __nv_bfloat16* row = g_Ain + (size_t)m * K3;
    row[k] = t0; row[CCH + k] = t1; row[2 * CCH + k] = t2;
}

// ---------------- packed dual-fp32 FMA (FFMA2 via PTX) ------------------------
__device__ __forceinline__ void fma2(uint64_t& d, uint64_t a, uint64_t b)
{
    asm("fma.rn.f32x2 %0, %1, %2, %0;" : "+l"(d) : "l"(a), "l"(b));
}

// ---------------- device body: fp32 SIMT GEMM [off | attn] -------------------
#define BM  128
#define BN  128
#define BK2 16
#define TM  8
#define TN  8
#define KQ  256

__device__ __forceinline__
void simt_oa_body(char* smemRaw, int crow, int ccol,
                  const float* __restrict__ A,
                  const float* __restrict__ Boff,
                  const float* __restrict__ Batt,
                  const float* __restrict__ bias_off,
                  const float* __restrict__ bias_att,
                  float* __restrict__ Coff,
                  float* __restrict__ Catt)
{
    float (*As)[BK2 * BM] = reinterpret_cast<float (*)[BK2 * BM]>(smemRaw);
    float (*Bs)[BK2 * BN] = reinterpret_cast<float (*)[BK2 * BN]>(
        smemRaw + 2 * BK2 * BM * sizeof(float));

    const float* B;  const float* bias;  float* C;  int NnB, NnC, colOff;
    if (ccol < 2) { B = Boff; bias = bias_off; C = Coff; NnB = 256; NnC = 256; colOff = ccol * BN; }
    else          { B = Batt; bias = bias_att; C = Catt; NnB = 128; NnC = 128; colOff = 0; }

    const int tid = threadIdx.x;
    const int threadRow = tid / (BN / TN);
    const int threadCol = tid % (BN / TN);

    const int rowA  = tid >> 2;
    const int colA4 = (tid & 3) * 4;
    const int rowB  = tid >> 5;
    const int colB4 = (tid & 31) * 4;

    const float* gA0 = A + (size_t)(crow * BM + rowA)      * KQ + colA4;
    const float* gA1 = A + (size_t)(crow * BM + rowA + 64) * KQ + colA4;
    const float* gB0 = B + (size_t)rowB       * NnB + colOff + colB4;
    const float* gB1 = B + (size_t)(rowB + 8) * NnB + colOff + colB4;

    uint64_t accp[TM * (TN / 2)];
    #pragma unroll
    for (int i = 0; i < TM * (TN / 2); i++) accp[i] = 0ull;

    float4 a0 = *reinterpret_cast<const float4*>(gA0);
    float4 a1 = *reinterpret_cast<const float4*>(gA1);
    float4 b0 = *reinterpret_cast<const float4*>(gB0);
    float4 b1 = *reinterpret_cast<const float4*>(gB1);
    {
        const float av0[4] = {a0.x, a0.y, a0.z, a0.w};
        const float av1[4] = {a1.x, a1.y, a1.z, a1.w};
        #pragma unroll
        for (int j = 0; j < 4; j++) {
            As[0][(colA4 + j) * BM + rowA]      = av0[j];
            As[0][(colA4 + j) * BM + rowA + 64] = av1[j];
        }
        *reinterpret_cast<float4*>(&Bs[0][rowB * BN + colB4])       = b0;
        *reinterpret_cast<float4*>(&Bs[0][(rowB + 8) * BN + colB4]) = b1;
    }
    __syncthreads();

    #pragma unroll
    for (int it = 0; it < KQ / BK2; it++) {
        const int buf = it & 1;
        const bool more = (it + 1) < (KQ / BK2);
        if (more) {
            const int k0 = (it + 1) * BK2;
            a0 = *reinterpret_cast<const float4*>(gA0 + k0);
            a1 = *reinterpret_cast<const float4*>(gA1 + k0);
            b0 = *reinterpret_cast<const float4*>(gB0 + (size_t)k0 * NnB);
            b1 = *reinterpret_cast<const float4*>(gB1 + (size_t)k0 * NnB);
        }

        #pragma unroll
        for (int k = 0; k < BK2; k++) {
            const float4 m0 = *reinterpret_cast<const float4*>(
                &As[buf][k * BM + threadRow * TM]);
            const float4 m1 = *reinterpret_cast<const float4*>(
                &As[buf][k * BM + threadRow * TM + 4]);
            const uint64_t* bp = reinterpret_cast<const uint64_t*>(
                &Bs[buf][k * BN + threadCol * TN]);
            uint64_t bn[4];
            bn[0] = bp[0]; bn[1] = bp[1]; bn[2] = bp[2]; bn[3] = bp[3];

            const float mv[8] = {m0.x, m0.y, m0.z, m0.w, m1.x, m1.y, m1.z, m1.w};
            #pragma unroll
            for (int i = 0; i < TM; i++) {
                const uint32_t mu = __float_as_uint(mv[i]);
                uint64_t mm;
                asm("mov.b64 %0, {%1, %1};" : "=l"(mm) : "r"(mu));
                #pragma unroll
                for (int j2 = 0; j2 < TN / 2; j2++)
                    fma2(accp[i * (TN / 2) + j2], mm, bn[j2]);
            }
        }

        if (more) {
            const float av0[4] = {a0.x, a0.y, a0.z, a0.w};
            const float av1[4] = {a1.x, a1.y, a1.z, a1.w};
            #pragma unroll
            for (int j = 0; j < 4; j++) {
                As[buf ^ 1][(colA4 + j) * BM + rowA]      = av0[j];
                As[buf ^ 1][(colA4 + j) * BM + rowA + 64] = av1[j];
            }
            *reinterpret_cast<float4*>(&Bs[buf ^ 1][rowB * BN + colB4])       = b0;
            *reinterpret_cast<float4*>(&Bs[buf ^ 1][(rowB + 8) * BN + colB4]) = b1;
        }
        __syncthreads();
    }

    float bj[TN];
    #pragma unroll
    for (int j = 0; j < TN; j++)
        bj[j] = bias[colOff + threadCol * TN + j];

    #pragma unroll
    for (int i = 0; i < TM; i++) {
        const int row = crow * BM + threadRow * TM + i;
        float o[TN];
        #pragma unroll
        for (int j2 = 0; j2 < TN / 2; j2++) {
            uint32_t lo, hi;
            asm("mov.b64 {%0, %1}, %2;" : "=r"(lo), "=r"(hi)
                : "l"(accp[i * (TN / 2) + j2]));
            o[2 * j2]     = __uint_as_float(lo) + bj[2 * j2];
            o[2 * j2 + 1] = __uint_as_float(hi) + bj[2 * j2 + 1];
        }
        #pragma unroll
        for (int j = 0; j < TN; j += 4) {
            const int col = colOff + threadCol * TN + j;
            *reinterpret_cast<float4*>(&C[(size_t)row * NnC + col]) =
                make_float4(o[j], o[j + 1], o[j + 2], o[j + 3]);
        }
    }
}

// ---------------- device body: bf16x3 TC GEMM, cp.async 4-stage ---------------
// MI = number of 16-row m-fragments per warp (4 -> 128-row tile, 2 -> 64-row).
#define GBK    32
#define GP     40
#define STAGES 4
#define OPELTS (128 * GP)
#define KSTEPS (KLOG3 / GBK)               // 24
#define GSMEM  (STAGES * 2 * OPELTS * 2)   // 81920 bytes

#define CP16(sm_, gp_) asm volatile( \
    "cp.async.cg.shared.global [%0], [%1], 16;" :: "r"(sm_), "l"(gp_))
#define CP_COMMIT()  asm volatile("cp.async.commit_group;")
#define CP_WAIT2()   asm volatile("cp.async.wait_group 2;")

template<int MI>
__device__ __forceinline__
void tc_gemm_body(char* smemRaw, int m0, int n0, int Nn,
                  const __nv_bfloat16* __restrict__ A,
                  const __nv_bfloat16* __restrict__ Bt,
                  const float* __restrict__ bias,
                  float* __restrict__ C,
                  __half* __restrict__ Chalf)
{
    __nv_bfloat16* As_ = reinterpret_cast<__nv_bfloat16*>(smemRaw);
    __nv_bfloat16* Bs_ = As_ + STAGES * OPELTS;

    const int tid  = threadIdx.x;
    const int wid  = tid >> 5;
    const int lane = tid & 31;
    const int wm = (wid >> 2) * (MI * 16);
    const int wn = (wid & 3) * 32;
    const int g8  = lane >> 2;
    const int tig = lane & 3;

    const int lrow = tid >> 2;
    const int lseg = tid & 3;
    const __nv_bfloat16* gA0 = A  + (size_t)(m0 + lrow)      * K3 + lseg * 8;
    const __nv_bfloat16* gA1 = A  + (size_t)(m0 + lrow + 64) * K3 + lseg * 8;
    const __nv_bfloat16* gB0 = Bt + (size_t)(n0 + lrow)      * K3 + lseg * 8;
    const __nv_bfloat16* gB1 = Bt + (size_t)(n0 + lrow + 64) * K3 + lseg * 8;
    const uint32_t sA0 = (uint32_t)__cvta_generic_to_shared(
        &As_[lrow * GP + lseg * 8]);
    const uint32_t sB0 = (uint32_t)__cvta_generic_to_shared(
        &Bs_[lrow * GP + lseg * 8]);

    float c[MI][4][4];
    #pragma unroll
    for (int mi = 0; mi < MI; mi++)
        #pragma unroll
        for (int ni = 0; ni < 4; ni++)
            #pragma unroll
            for (int r = 0; r < 4; r++) c[mi][ni][r] = 0.0f;

    auto load_stage = [&](int st) {
        const int slot = st & (STAGES - 1);
        const int k0   = st * GBK;
        const int seg  = k0 >> 8;
        const int ka   = c_amap[seg] * CCH + (k0 & 255);
        const int kb   = c_bmap[seg] * CCH + (k0 & 255);
        const uint32_t so = slot * OPELTS * 2;
        CP16(sA0 + so,               gA0 + ka);
        if (MI == 4) CP16(sA0 + so + 64 * GP * 2, gA1 + ka);
        CP16(sB0 + so,               gB0 + kb);
        CP16(sB0 + so + 64 * GP * 2, gB1 + kb);
    };

    load_stage(0); CP_COMMIT();
    load_stage(1); CP_COMMIT();
    load_stage(2); CP_COMMIT();

    for (int kt = 0; kt < KSTEPS; kt++) {
        CP_WAIT2();
        __syncthreads();
        const __nv_bfloat16* Asl = As_ + (kt & (STAGES - 1)) * OPELTS;
        const __nv_bfloat16* Bsl = Bs_ + (kt & (STAGES - 1)) * OPELTS;

        #pragma unroll
        for (int h = 0; h < 2; h++) {
            uint32_t afr[MI][4], bfr[4][2];
            #pragma unroll
            for (int mi = 0; mi < MI; mi++) {
                const int rb = (wm + mi * 16 + g8) * GP + h * 16 + tig * 2;
                afr[mi][0] = *reinterpret_cast<const uint32_t*>(&Asl[rb]);
                afr[mi][1] = *reinterpret_cast<const uint32_t*>(&Asl[rb + 8 * GP]);
                afr[mi][2] = *reinterpret_cast<const uint32_t*>(&Asl[rb + 8]);
                afr[mi][3] = *reinterpret_cast<const uint32_t*>(&Asl[rb + 8 * GP + 8]);
            }
            #pragma unroll
            for (int ni = 0; ni < 4; ni++) {
                const int rb = (wn + ni * 8 + g8) * GP + h * 16 + tig * 2;
                bfr[ni][0] = *reinterpret_cast<const uint32_t*>(&Bsl[rb]);
                bfr[ni][1] = *reinterpret_cast<const uint32_t*>(&Bsl[rb + 8]);
            }
            #pragma unroll
            for (int mi = 0; mi < MI; mi++)
                #pragma unroll
                for (int ni = 0; ni < 4; ni++) {
                    asm volatile(
                        "mma.sync.aligned.m16n8k16.row.col.f32.bf16.bf16.f32 "
                        "{%0,%1,%2,%3}, {%4,%5,%6,%7}, {%8,%9}, {%0,%1,%2,%3};"
                        : "+f"(c[mi][ni][0]), "+f"(c[mi][ni][1]),
                          "+f"(c[mi][ni][2]), "+f"(c[mi][ni][3])
                        : "r"(afr[mi][0]), "r"(afr[mi][1]),
                          "r"(afr[mi][2]), "r"(afr[mi][3]),
                          "r"(bfr[ni][0]), "r"(bfr[ni][1]));
                }
        }

        if (kt + STAGES - 1 < KSTEPS) load_stage(kt + STAGES - 1);
        CP_COMMIT();
    }

    #pragma unroll
    for (int mi = 0; mi < MI; mi++) {
        const int row = m0 + wm + mi * 16 + g8;
        #pragma unroll
        for (int ni = 0; ni < 4; ni++) {
            const int col = n0 + wn + ni * 8 + tig * 2;
            const float b0 = bias[col], b1 = bias[col + 1];
            const float v00 = c[mi][ni][0] + b0, v01 = c[mi][ni][1] + b1;
            const float v10 = c[mi][ni][2] + b0, v11 = c[mi][ni][3] + b1;
            if (Chalf) {
                *reinterpret_cast<__half2*>(&Chalf[(size_t)row * Nn + col]) =
                    __floats2half2_rn(v00, v01);
                *reinterpret_cast<__half2*>(&Chalf[(size_t)(row + 8) * Nn + col]) =
                    __floats2half2_rn(v10, v11);
            } else {
                *reinterpret_cast<float2*>(&C[(size_t)row * Nn + col]) =
                    make_float2(v00, v01);
                *reinterpret_cast<float2*>(&C[(size_t)(row + 8) * Nn + col]) =
                    make_float2(v10, v11);
            }
        }
    }
}

// ---------------- mega kernel: TC value tiles + SIMT off/attn tiles ----------
// 850 blocks. role = bid % 5: 0,1 -> TC value (340 tiles); 2,3,4 -> SIMT oa (510).
__global__ __launch_bounds__(256)
void mega_gemm(const __nv_bfloat16* __restrict__ Ain,
               const __nv_bfloat16* __restrict__ Btv,
               const float* __restrict__ b_val,
               const float* __restrict__ query,
               const float* __restrict__ Boff,
               const float* __restrict__ Batt,
               const float* __restrict__ bias_off,
               const float* __restrict__ bias_att,
               float* __restrict__ Coff,
               float* __restrict__ Catt)
{
    extern __shared__ char smemRaw[];
    const int bid  = blockIdx.x;
    const int role = bid % 5;
    const int grp  = bid / 5;          // 0..169
    if (role < 2) {
        const int idx = grp * 2 + role;        // 0..339
        tc_gemm_body<4>(smemRaw, (idx >> 1) * 128, (idx & 1) * 128, CCH,
                        Ain, Btv, b_val, nullptr, g_valueh);
    } else {
        const int idx = grp * 3 + (role - 2);  // 0..509
        simt_oa_body(smemRaw, idx / 3, idx % 3,
                     query, Boff, Batt, bias_off, bias_att, Coff, Catt);
    }
}

// ---------------- out projection: 64x128 tiles (tail reduction) --------------
__global__ __launch_bounds__(256)
void gemm_out(const __nv_bfloat16* __restrict__ A,
              const __nv_bfloat16* __restrict__ Bt,
              const float* __restrict__ bias,
              float* __restrict__ C)
{
    extern __shared__ char smemRaw[];
    tc_gemm_body<2>(smemRaw, blockIdx.y * 64, blockIdx.x * 128, CCH,
                    A, Bt, bias, C, nullptr);
}

// ---------------- sampling: fp16 gathers, 8 queries/block --------------------
__global__ __launch_bounds__(256)
void sample_kernel(const float* __restrict__ refp)
{
    const int nq0 = blockIdx.x * QPB;
    const int tid = threadIdx.x;

    __shared__ float4 s_w[QPB * 128];
    __shared__ int4   s_t[QPB * 128];

    #pragma unroll
    for (int rep = 0; rep < QPB * 128 / 256; rep++) {   // 4 reps
        const int task = tid + rep * 256;
        const int q    = task >> 7;
        const int rest = task & 127;
        const int l    = (rest & 15) >> 2;
        const int nq   = nq0 + q;

        float logit = g_attn[(size_t)nq * 128 + rest];
        float mx = logit;
        #pragma unroll
        for (int m = 8; m; m >>= 1)
            mx = fmaxf(mx, __shfl_xor_sync(0xffffffffu, mx, m, 16));
        float e = __expf(logit - mx);
        float ssum = e;
        #pragma unroll
        for (int m = 8; m; m >>= 1)
            ssum += __shfl_xor_sync(0xffffffffu, ssum, m, 16);
        const float aw = e * (1.0f / ssum);

        const int W  = 64 >> l;
        const int S0 = (16384 - (16384 >> (2 * l))) / 3;

        const float2 off = *reinterpret_cast<const float2*>(
            &g_off[(size_t)nq * CCH + rest * 2]);
        const float2 rp  = *reinterpret_cast<const float2*>(
            &refp[((size_t)nq * NL + l) * 2]);

        const float locx = fminf(fmaxf(rp.x + off.x, 0.0f), 1.0f);
        const float locy = fminf(fmaxf(rp.y + off.y, 0.0f), 1.0f);
        const float x = locx * (float)W - 0.5f;
        const float y = locy * (float)W - 0.5f;
        const int xf = (int)floorf(x);
        const int yf = (int)floorf(y);
        const int x0i = min(max(xf,     0), W - 1);
        const int x1i = min(max(xf + 1, 0), W - 1);
        const int y0i = min(max(yf,     0), W - 1);
        const int y1i = min(max(yf + 1, 0), W - 1);
        const float wx1 = (float)x1i - x;
        const float wx0 = x - (float)x0i;
        const float wy1 = (float)y1i - y;
        const float wy0 = y - (float)y0i;

        s_w[task] = make_float4(wx1 * wy1 * aw, wx1 * wy0 * aw,
                                wx0 * wy1 * aw, wx0 * wy0 * aw);
        s_t[task] = make_int4(S0 + y0i * W + x0i,
                              S0 + y1i * W + x0i,
                              S0 + y0i * W + x1i,
                              S0 + y1i * W + x1i);
    }
    __syncthreads();

    const int q  = tid >> 5;        // 0..7
    const int r  = tid & 31;
    const int h  = r >> 2;          // 0..7
    const int d8 = r & 3;           // 0..3 (8-half group)
    const int nq = nq0 + q;
    const int n  = nq / LQ;

    const __half* vb = g_valueh + (size_t)n * LEN_IN * CCH + h * DH + d8 * 8;

    float acc[8];
    #pragma unroll
    for (int j = 0; j < 8; j++) acc[j] = 0.0f;
    const int tb0 = q * 128 + h * 16;

    #pragma unroll
    for (int i = 0; i < 16; i++) {
        const float4 w  = s_w[tb0 + i];
        const int4   tt = s_t[tb0 + i];
        const uint4 ua = *reinterpret_cast<const uint4*>(vb + (size_t)tt.x * CCH);
        const uint4 ub = *reinterpret_cast<const uint4*>(vb + (size_t)tt.y * CCH);
        const uint4 uc = *reinterpret_cast<const uint4*>(vb + (size_t)tt.z * CCH);
        const uint4 ud = *reinterpret_cast<const uint4*>(vb + (size_t)tt.w * CCH);
        const __half2* ha = reinterpret_cast<const __half2*>(&ua);
        const __half2* hb = reinterpret_cast<const __half2*>(&ub);
        const __half2* hc = reinterpret_cast<const __half2*>(&uc);
        const __half2* hd = reinterpret_cast<const __half2*>(&ud);
        #pragma unroll
        for (int p = 0; p < 4; p++) {
            const float2 fa = __half22float2(ha[p]);
            const float2 fb = __half22float2(hb[p]);
            const float2 fc = __half22float2(hc[p]);
            const float2 fd = __half22float2(hd[p]);
            acc[2*p]   += w.x * fa.x + w.y * fb.x + w.z * fc.x + w.w * fd.x;
            acc[2*p+1] += w.x * fa.y + w.y * fb.y + w.z * fc.y + w.w * fd.y;
        }
    }

    // fused split (t0,t1 only — x3 out-GEMM never reads the t2 segment)
    __align__(8) __nv_bfloat16 t0[8], t1[8];
    #pragma unroll
    for (int j = 0; j < 8; j++) {
        t0[j] = __float2bfloat16(acc[j]);
        t1[j] = __float2bfloat16(acc[j] - __bfloat162float(t0[j]));
    }

    __nv_bfloat16* row = g_As + (size_t)nq * K3 + h * DH + d8 * 8;
    *reinterpret_cast<ushort4*>(row)           = *reinterpret_cast<ushort4*>(t0);
    *reinterpret_cast<ushort4*>(row + 4)       = *reinterpret_cast<ushort4*>(t0 + 4);
    *reinterpret_cast<ushort4*>(row + CCH)     = *reinterpret_cast<ushort4*>(t1);
    *reinterpret_cast<ushort4*>(row + CCH + 4) = *reinterpret_cast<ushort4*>(t1 + 4);
}

// ---------------- launch ------------------------------------------------------
extern "C" void kernel_launch(void* const* d_in, const int* in_sizes, int n_in,
                              void* d_out, int out_size)
{
    const float* query  = (const float*)d_in[0];
    const float* refp   = (const float*)d_in[1];
    const float* inputf = (const float*)d_in[2];
    const float* w_off  = (const float*)d_in[5];
    const float* b_off  = (const float*)d_in[6];
    const float* w_attn = (const float*)d_in[7];
    const float* b_attn = (const float*)d_in[8];
    const float* w_val  = (const float*)d_in[9];
    const float* b_val  = (const float*)d_in[10];
    const float* w_out  = (const float*)d_in[11];
    const float* b_out  = (const float*)d_in[12];
    float* out = (float*)d_out;

    cudaFuncSetAttribute(gemm_out,
                         cudaFuncAttributeMaxDynamicSharedMemorySize, GSMEM);
    cudaFuncSetAttribute(mega_gemm,
                         cudaFuncAttributeMaxDynamicSharedMemorySize, GSMEM);

    float *go, *ga;
    cudaGetSymbolAddress((void**)&go, g_off);
    cudaGetSymbolAddress((void**)&ga, g_attn);
    __nv_bfloat16 *ain, *as, *btv, *btw;
    cudaGetSymbolAddress((void**)&ain, g_Ain);
    cudaGetSymbolAddress((void**)&as,  g_As);
    cudaGetSymbolAddress((void**)&btv, g_Btv);
    cudaGetSymbolAddress((void**)&btw, g_Btw);

    const dim3 blk(256);

    // all splits in one launch (w_val, w_out, input_flatten)
    split_all<<<512 + MROWS, blk>>>(w_val, w_out, inputf);

    // value (TC -> fp16 out) + off/attn (SIMT fp32 FFMA2) fused — pipe overlap
    mega_gemm<<<850, blk, GSMEM>>>(ain, btv, b_val,
                                   query, w_off, w_attn, b_off, b_attn, go, ga);

    // sampling (fp16 gathers) + fused split of sampled output
    sample_kernel<<<MROWS / QPB, blk>>>(refp);

    // out = samp @ w_out + b_out  (TC bf16x3, 64x128 tiles to cut wave tail)
    gemm_out<<<dim3(2, MROWS / 64), blk, GSMEM>>>(as, btw, b_out, out);
}